// round 8
// baseline (speedup 1.0000x reference)
#include <cuda_runtime.h>
#include <math.h>

#define THREADS 256
#define WARPS (THREADS / 32)
#define ROWS 8        // rows per CTA, processed sequentially
#define UNROLL 8      // 2048 float4 per row / 256 threads

// GLIF single timestep, fused matvec + elementwise.
// Single-wave persistent-ish grid: 1024 CTAs x 8 rows each.
// No per-row block barrier -> rows/CTAs desynchronize, DRAM stays fed.
// out[0:N) = v_new, out[N:2N) = spiked_soft.
__global__ __launch_bounds__(THREADS, 7)
void glif_kernel(const float* __restrict__ x_in,
                 const float* __restrict__ w,
                 const float* __restrict__ v0,
                 const float* __restrict__ g,
                 const float* __restrict__ v_rest,
                 const float* __restrict__ tau_m,
                 const float* __restrict__ theta_s,
                 const float* __restrict__ theta_v,
                 float* __restrict__ out,
                 int n)
{
    __shared__ float psum[ROWS * WARPS];   // [row][warp] partials, 256 B

    const int tid  = threadIdx.x;
    const int warp = tid >> 5;
    const int lane = tid & 31;
    const int row0 = blockIdx.x * ROWS;

    const float4* __restrict__ g4 = reinterpret_cast<const float4*>(g);

    for (int ir = 0; ir < ROWS; ir++) {
        const float4* __restrict__ wrow =
            reinterpret_cast<const float4*>(w + (size_t)(row0 + ir) * (size_t)n);

        float a0 = 0.f, a1 = 0.f, a2 = 0.f, a3 = 0.f;
        #pragma unroll
        for (int u = 0; u < UNROLL; u++) {
            float4 wv = wrow[tid + u * THREADS];
            float4 gv = g4[tid + u * THREADS];   // L1-resident after first row
            a0 = fmaf(wv.x, gv.x, a0);
            a1 = fmaf(wv.y, gv.y, a1);
            a2 = fmaf(wv.z, gv.z, a2);
            a3 = fmaf(wv.w, gv.w, a3);
        }
        float acc = (a0 + a1) + (a2 + a3);

        // Warp-level reduction only — no block barrier inside the row loop.
        #pragma unroll
        for (int off = 16; off > 0; off >>= 1)
            acc += __shfl_xor_sync(0xFFFFFFFFu, acc, off);

        if (lane == 0) psum[ir * WARPS + warp] = acc;
    }

    __syncthreads();

    // Final reduce: 64 threads, one group of 8 per row.
    if (tid < ROWS * WARPS) {
        float s = psum[tid];
        s += __shfl_xor_sync(0xFFFFFFFFu, s, 1);
        s += __shfl_xor_sync(0xFFFFFFFFu, s, 2);
        s += __shfl_xor_sync(0xFFFFFFFFu, s, 4);

        if ((tid & 7) == 0) {
            const int row = row0 + (tid >> 3);

            const float xi  = x_in[row];
            const float vr  = v_rest[row];
            const float tm  = tau_m[row];
            const float ths = theta_s[row];
            const float thv = theta_v[row];
            const float vin = v0[row];

            // I = sigmoid(w@g + x_in)
            const float z = s + xi;
            const float I = 1.0f / (1.0f + expf(-z));

            // membrane integration
            const float v = vin + (vr - vin + I) / tm;

            const float thresh = ths + thv;
            // surrogate spike (accurate exp: value can be ~1e-20)
            const float spiked_soft = 1.0f / (1.0f + expf(-(v - thresh)));
            // hard spike + reset-or-keep
            const float v_new = (v >= thresh) ? vr : v;

            out[row]     = v_new;
            out[n + row] = spiked_soft;
        }
    }
}

extern "C" void kernel_launch(void* const* d_in, const int* in_sizes, int n_in,
                              void* d_out, int out_size)
{
    // metadata order: x_in, w, v, g, v_rest, tau_m, tau_g, theta_s, theta_v, b_s, a_v, b_v
    const float* x_in    = (const float*)d_in[0];
    const float* w       = (const float*)d_in[1];
    const float* v       = (const float*)d_in[2];
    const float* g       = (const float*)d_in[3];
    const float* v_rest  = (const float*)d_in[4];
    const float* tau_m   = (const float*)d_in[5];
    // d_in[6] = tau_g (unused by returned outputs)
    const float* theta_s = (const float*)d_in[7];
    const float* theta_v = (const float*)d_in[8];
    // d_in[9..11] = b_s, a_v, b_v (only affect discarded hidden state)

    float* out = (float*)d_out;
    const int n = in_sizes[0];  // 8192

    glif_kernel<<<n / ROWS, THREADS>>>(x_in, w, v, g, v_rest, tau_m,
                                       theta_s, theta_v, out, n);
}

// round 13
// speedup vs baseline: 1.2199x; 1.2199x over previous
#include <cuda_runtime.h>
#include <math.h>

#define THREADS   256
#define WARPS     (THREADS / 32)
#define N_FIXED   8192
#define HALF_VEC  (N_FIXED / 4 / 2)   // 1024 float4 per half-row
#define PER_THR   (HALF_VEC / THREADS) // 4

// Self-cleaning cross-CTA combine scratch (zero-init at module load; each
// finisher CTA resets its row's slots, so every launch sees zeros).
__device__ float        g_acc[N_FIXED];
__device__ unsigned int g_cnt[N_FIXED];

// GLIF single timestep, fused matvec + elementwise.
// Two CTAs per row (grid = 2N): each reads half a row (16 KB), reduces,
// atomically combines; the second arriver runs the scalar epilogue.
// out[0:N) = v_new, out[N:2N) = spiked_soft.
__global__ __launch_bounds__(THREADS)
void glif_kernel(const float* __restrict__ x_in,
                 const float* __restrict__ w,
                 const float* __restrict__ v0,
                 const float* __restrict__ g,
                 const float* __restrict__ v_rest,
                 const float* __restrict__ tau_m,
                 const float* __restrict__ theta_s,
                 const float* __restrict__ theta_v,
                 float* __restrict__ out,
                 int n)
{
    const int row  = blockIdx.x >> 1;
    const int half = blockIdx.x & 1;
    const int tid  = threadIdx.x;

    const float4* __restrict__ wrow =
        reinterpret_cast<const float4*>(w + (size_t)row * (size_t)n) + half * HALF_VEC;
    const float4* __restrict__ g4 =
        reinterpret_cast<const float4*>(g) + half * HALF_VEC;

    // Front-batch the 4 w loads (streaming hint: w is read exactly once).
    float4 wv[PER_THR];
    #pragma unroll
    for (int u = 0; u < PER_THR; u++)
        wv[u] = __ldcs(&wrow[tid + u * THREADS]);

    float a0 = 0.f, a1 = 0.f, a2 = 0.f, a3 = 0.f;
    #pragma unroll
    for (int u = 0; u < PER_THR; u++) {
        float4 gv = g4[tid + u * THREADS];   // L1/L2-resident (32 KB total)
        a0 = fmaf(wv[u].x, gv.x, a0);
        a1 = fmaf(wv[u].y, gv.y, a1);
        a2 = fmaf(wv[u].z, gv.z, a2);
        a3 = fmaf(wv[u].w, gv.w, a3);
    }
    float acc = (a0 + a1) + (a2 + a3);

    // Warp reduction
    #pragma unroll
    for (int off = 16; off > 0; off >>= 1)
        acc += __shfl_xor_sync(0xFFFFFFFFu, acc, off);

    __shared__ float warp_sums[WARPS];
    if ((tid & 31) == 0) warp_sums[tid >> 5] = acc;
    __syncthreads();

    if (tid == 0) {
        float s = 0.0f;
        #pragma unroll
        for (int wgi = 0; wgi < WARPS; wgi++) s += warp_sums[wgi];

        // Cross-CTA combine: exactly 2 contributors per row.
        const float        old  = atomicAdd(&g_acc[row], s);
        const unsigned int done = atomicAdd(&g_cnt[row], 1u);

        if (done == 1u) {
            // I'm second: total = other half's sum + mine (order-independent).
            const float total = old + s;

            // Reset scratch for the next launch (self-cleaning).
            g_acc[row] = 0.0f;
            g_cnt[row] = 0u;

            // GLIF elementwise epilogue for this neuron
            const float xi  = x_in[row];
            const float vr  = v_rest[row];
            const float tm  = tau_m[row];
            const float ths = theta_s[row];
            const float thv = theta_v[row];
            const float vin = v0[row];

            // I = sigmoid(w@g + x_in)
            const float z = total + xi;
            const float I = 1.0f / (1.0f + expf(-z));

            // membrane integration
            const float v = vin + (vr - vin + I) / tm;

            const float thresh = ths + thv;
            // surrogate spike (accurate exp: value can be ~1e-20)
            const float spiked_soft = 1.0f / (1.0f + expf(-(v - thresh)));
            // hard spike + reset-or-keep
            const float v_new = (v >= thresh) ? vr : v;

            out[row]     = v_new;
            out[n + row] = spiked_soft;
        }
    }
}

extern "C" void kernel_launch(void* const* d_in, const int* in_sizes, int n_in,
                              void* d_out, int out_size)
{
    // metadata order: x_in, w, v, g, v_rest, tau_m, tau_g, theta_s, theta_v, b_s, a_v, b_v
    const float* x_in    = (const float*)d_in[0];
    const float* w       = (const float*)d_in[1];
    const float* v       = (const float*)d_in[2];
    const float* g       = (const float*)d_in[3];
    const float* v_rest  = (const float*)d_in[4];
    const float* tau_m   = (const float*)d_in[5];
    // d_in[6] = tau_g (unused by returned outputs)
    const float* theta_s = (const float*)d_in[7];
    const float* theta_v = (const float*)d_in[8];
    // d_in[9..11] = b_s, a_v, b_v (only affect discarded hidden state)

    float* out = (float*)d_out;
    const int n = in_sizes[0];  // 8192

    glif_kernel<<<2 * n, THREADS>>>(x_in, w, v, g, v_rest, tau_m,
                                    theta_s, theta_v, out, n);
}

// round 15
// speedup vs baseline: 3.0233x; 2.4783x over previous
#include <cuda_runtime.h>
#include <math.h>

#define THREADS 256
#define WARPS   (THREADS / 32)
#define MAXN    8192
#define CTHREADS 1024   // compaction kernel block size

// Deterministic sparse-compaction scratch. Rewritten in full every launch
// (g_nnz written last by thread 0 of compact_g), so graph replays are clean.
__device__ int   g_nnz;
__device__ int   g_idx[MAXN];
__device__ float g_val[MAXN];

// ---------------------------------------------------------------------------
// Kernel A: ordered compaction of nonzeros of g (index-ordered -> the later
// gather accumulates in a fixed order => deterministic output for ANY input).
// Single CTA, block-wide scan per 1024-chunk.
// ---------------------------------------------------------------------------
__global__ __launch_bounds__(CTHREADS)
void compact_g(const float* __restrict__ g, int n)
{
    __shared__ int warp_tot[CTHREADS / 32];
    __shared__ int base_sh;

    const int tid  = threadIdx.x;
    const int lane = tid & 31;
    const int wrp  = tid >> 5;

    if (tid == 0) base_sh = 0;
    __syncthreads();

    for (int c = 0; c < n; c += CTHREADS) {
        const int i = c + tid;
        const float gv = (i < n) ? g[i] : 0.0f;
        const bool p = (gv != 0.0f);

        const unsigned mask = __ballot_sync(0xFFFFFFFFu, p);
        const int prefix = __popc(mask & ((1u << lane) - 1u));
        if (lane == 0) warp_tot[wrp] = __popc(mask);
        __syncthreads();

        int woff = 0, chunk_tot = 0;
        #pragma unroll
        for (int k = 0; k < CTHREADS / 32; k++) {
            const int t = warp_tot[k];
            if (k < wrp) woff += t;
            chunk_tot += t;
        }

        if (p) {
            const int pos = base_sh + woff + prefix;
            g_idx[pos] = i;
            g_val[pos] = gv;
        }
        __syncthreads();
        if (tid == 0) base_sh += chunk_tot;
        __syncthreads();
    }

    if (tid == 0) g_nnz = base_sh;
}

// ---------------------------------------------------------------------------
// Kernel B: GLIF timestep. One CTA per row.
//   nnz == 0       -> matvec term is exactly 0.0; epilogue only.
//   nnz small      -> gather only the nonzero columns (exact: skipped terms
//                     contribute exactly 0.0 for finite w).
//   nnz large      -> dense row dot (proven path, rel_err 3.2e-9).
// out[0:N) = v_new, out[N:2N) = spiked_soft.
// ---------------------------------------------------------------------------
__global__ __launch_bounds__(THREADS)
void glif_apply(const float* __restrict__ x_in,
                const float* __restrict__ w,
                const float* __restrict__ v0,
                const float* __restrict__ g,
                const float* __restrict__ v_rest,
                const float* __restrict__ tau_m,
                const float* __restrict__ theta_s,
                const float* __restrict__ theta_v,
                float* __restrict__ out,
                int n)
{
    const int row = blockIdx.x;
    const int tid = threadIdx.x;
    const int nnz = g_nnz;

    float total = 0.0f;

    if (nnz != 0) {
        float acc = 0.0f;
        const float* __restrict__ wr = w + (size_t)row * (size_t)n;

        if (nnz <= n / 8) {
            // Sparse gather over the index-ordered compact list.
            for (int k = tid; k < nnz; k += THREADS)
                acc = fmaf(wr[g_idx[k]], g_val[k], acc);
        } else {
            // Dense row dot (R2 path).
            const float4* __restrict__ w4 = reinterpret_cast<const float4*>(wr);
            const float4* __restrict__ g4 = reinterpret_cast<const float4*>(g);
            const int nvec = n >> 2;
            float a0 = 0.f, a1 = 0.f, a2 = 0.f, a3 = 0.f;
            #pragma unroll 8
            for (int j = tid; j < nvec; j += THREADS) {
                float4 wv = w4[j];
                float4 gv = g4[j];
                a0 = fmaf(wv.x, gv.x, a0);
                a1 = fmaf(wv.y, gv.y, a1);
                a2 = fmaf(wv.z, gv.z, a2);
                a3 = fmaf(wv.w, gv.w, a3);
            }
            acc = (a0 + a1) + (a2 + a3);
        }

        // Block reduction (fixed tree order -> deterministic).
        #pragma unroll
        for (int off = 16; off > 0; off >>= 1)
            acc += __shfl_xor_sync(0xFFFFFFFFu, acc, off);

        __shared__ float warp_sums[WARPS];
        if ((tid & 31) == 0) warp_sums[tid >> 5] = acc;
        __syncthreads();

        if (tid == 0) {
            float s = 0.0f;
            #pragma unroll
            for (int wgi = 0; wgi < WARPS; wgi++) s += warp_sums[wgi];
            total = s;
        }
    }

    if (tid == 0) {
        // GLIF elementwise epilogue for this neuron
        const float xi  = x_in[row];
        const float vr  = v_rest[row];
        const float tm  = tau_m[row];
        const float ths = theta_s[row];
        const float thv = theta_v[row];
        const float vin = v0[row];

        // I = sigmoid(w@g + x_in)
        const float z = total + xi;
        const float I = 1.0f / (1.0f + expf(-z));

        // membrane integration
        const float v = vin + (vr - vin + I) / tm;

        const float thresh = ths + thv;
        // surrogate spike (accurate exp: value can be ~1e-20)
        const float spiked_soft = 1.0f / (1.0f + expf(-(v - thresh)));
        // hard spike + reset-or-keep
        const float v_new = (v >= thresh) ? vr : v;

        out[row]     = v_new;
        out[n + row] = spiked_soft;
    }
}

extern "C" void kernel_launch(void* const* d_in, const int* in_sizes, int n_in,
                              void* d_out, int out_size)
{
    // metadata order: x_in, w, v, g, v_rest, tau_m, tau_g, theta_s, theta_v, b_s, a_v, b_v
    const float* x_in    = (const float*)d_in[0];
    const float* w       = (const float*)d_in[1];
    const float* v       = (const float*)d_in[2];
    const float* g       = (const float*)d_in[3];
    const float* v_rest  = (const float*)d_in[4];
    const float* tau_m   = (const float*)d_in[5];
    // d_in[6] = tau_g (unused by returned outputs)
    const float* theta_s = (const float*)d_in[7];
    const float* theta_v = (const float*)d_in[8];
    // d_in[9..11] = b_s, a_v, b_v (only affect discarded hidden state)

    float* out = (float*)d_out;
    const int n = in_sizes[0];  // 8192

    compact_g<<<1, CTHREADS>>>(g, n);
    glif_apply<<<n, THREADS>>>(x_in, w, v, g, v_rest, tau_m,
                               theta_s, theta_v, out, n);
}